// round 2
// baseline (speedup 1.0000x reference)
#include <cuda_runtime.h>

// Problem constants (fixed shapes from reference)
#define T_TOK 8192      // B*S = 4*2048
#define MDIM  1024
#define NEXP  8
#define DFFD  4096
#define CAP   1280      // int(1.25 * 8192 / 8)

// ---------------- device scratch (no allocations allowed) ----------------
__device__ float g_disp[(size_t)NEXP * CAP * MDIM];   //  41.9 MB
__device__ float g_h   [(size_t)NEXP * CAP * DFFD];   // 167.8 MB
__device__ float g_oute[(size_t)NEXP * CAP * MDIM];   //  41.9 MB
__device__ int   g_expert[T_TOK];
__device__ float g_gate[T_TOK];
__device__ int   g_slot[T_TOK];                       // e*CAP+pos or -1

// ---------------- K1: gating (one warp per token) ----------------
__global__ void gate_kernel(const float* __restrict__ x,
                            const float* __restrict__ wg)
{
    int warp = (blockIdx.x * blockDim.x + threadIdx.x) >> 5;
    int lane = threadIdx.x & 31;
    if (warp >= T_TOK) return;

    const float* xr = x + (size_t)warp * MDIM;
    float acc[8] = {0.f,0.f,0.f,0.f,0.f,0.f,0.f,0.f};

    #pragma unroll 4
    for (int i = 0; i < MDIM / 32; i++) {
        int m = i * 32 + lane;
        float xv = __ldg(xr + m);
        const float4* w4 = reinterpret_cast<const float4*>(wg + (size_t)m * NEXP);
        float4 a = w4[0], b = w4[1];
        acc[0] += xv * a.x; acc[1] += xv * a.y;
        acc[2] += xv * a.z; acc[3] += xv * a.w;
        acc[4] += xv * b.x; acc[5] += xv * b.y;
        acc[6] += xv * b.z; acc[7] += xv * b.w;
    }
    #pragma unroll
    for (int e = 0; e < 8; e++)
        #pragma unroll
        for (int off = 16; off > 0; off >>= 1)
            acc[e] += __shfl_xor_sync(0xffffffffu, acc[e], off);

    if (lane == 0) {
        float mx = acc[0]; int bi = 0;
        #pragma unroll
        for (int e = 1; e < 8; e++)
            if (acc[e] > mx) { mx = acc[e]; bi = e; }
        float s = 0.f;
        #pragma unroll
        for (int e = 0; e < 8; e++) s += expf(acc[e] - mx);
        g_expert[warp] = bi;
        g_gate[warp]   = 1.0f / s;   // softmax prob of the argmax expert
    }
}

// ---------------- K2: ordered per-expert rank (single block scan) ----------------
__global__ void pos_kernel()
{
    __shared__ int hist[1024][8];
    int tid = threadIdx.x;          // 1024 threads, 8 tokens each
    int base_t = tid * 8;

    int cnt[8] = {0,0,0,0,0,0,0,0};
    int loc[8];
    #pragma unroll
    for (int i = 0; i < 8; i++) {
        int e = g_expert[base_t + i];
        loc[i] = e;
        cnt[e]++;
    }
    #pragma unroll
    for (int e = 0; e < 8; e++) hist[tid][e] = cnt[e];
    __syncthreads();

    // Hillis-Steele inclusive scan over 1024 threads (8 lanes each)
    for (int off = 1; off < 1024; off <<= 1) {
        int v[8];
        bool p = (tid >= off);
        if (p) {
            #pragma unroll
            for (int e = 0; e < 8; e++) v[e] = hist[tid - off][e];
        }
        __syncthreads();
        if (p) {
            #pragma unroll
            for (int e = 0; e < 8; e++) hist[tid][e] += v[e];
        }
        __syncthreads();
    }

    int run[8];
    #pragma unroll
    for (int e = 0; e < 8; e++) run[e] = hist[tid][e] - cnt[e]; // exclusive base

    #pragma unroll
    for (int i = 0; i < 8; i++) {
        int e = loc[i];
        int p = run[e]++;
        g_slot[base_t + i] = (p < CAP) ? (e * CAP + p) : -1;
    }
}

// ---------------- K3: scatter tokens into per-expert buffers ----------------
__global__ void scatter_kernel(const float* __restrict__ x)
{
    int t = blockIdx.x;
    int s = g_slot[t];
    if (s < 0) return;
    const float4* src = reinterpret_cast<const float4*>(x + (size_t)t * MDIM);
    float4* dst = reinterpret_cast<float4*>(g_disp + (size_t)s * MDIM);
    dst[threadIdx.x] = src[threadIdx.x];   // 256 threads * float4 = 1024 floats
}

// ---------------- GEMM: C[M,N] = op(A[M,K] @ B[K,N] + bias[N]) ----------------
// lda = K, ldb = ldc = N (holds for both FFN GEMMs). Dims divide tiles exactly.
template<bool RELU>
__global__ __launch_bounds__(256, 2)
void gemm128(const float* __restrict__ Ag, const float* __restrict__ Bg,
             const float* __restrict__ biasg, float* __restrict__ Cg,
             int N, int K, size_t eA, size_t eB, size_t eC, int eBias)
{
    const int BM = 128, BN = 128, BK = 16;
    __shared__ float As[BK][BM];
    __shared__ float Bs[BK][BN];

    const float* A = Ag + blockIdx.z * eA + (size_t)(blockIdx.y * BM) * K;
    const float* B = Bg + blockIdx.z * eB + (size_t)(blockIdx.x * BN);
    const float* bias = biasg + blockIdx.z * eBias + blockIdx.x * BN;
    float* C = Cg + blockIdx.z * eC + (size_t)(blockIdx.y * BM) * N + blockIdx.x * BN;

    int tid = threadIdx.x;
    int tx = tid & 15;          // 16 thread cols
    int ty = tid >> 4;          // 16 thread rows

    int arow  = tid >> 2;          // 0..63 (second half at +64)
    int acol4 = (tid & 3) * 4;     // 0,4,8,12
    int brow  = tid >> 5;          // 0..7 (second half at +8)
    int bcol4 = (tid & 31) * 4;

    float acc[8][8];
    #pragma unroll
    for (int i = 0; i < 8; i++)
        #pragma unroll
        for (int j = 0; j < 8; j++) acc[i][j] = 0.f;

    for (int k0 = 0; k0 < K; k0 += BK) {
        float4 a0 = *reinterpret_cast<const float4*>(A + (size_t)arow * K + k0 + acol4);
        float4 a1 = *reinterpret_cast<const float4*>(A + (size_t)(arow + 64) * K + k0 + acol4);
        float4 b0 = *reinterpret_cast<const float4*>(B + (size_t)(k0 + brow) * N + bcol4);
        float4 b1 = *reinterpret_cast<const float4*>(B + (size_t)(k0 + brow + 8) * N + bcol4);

        As[acol4 + 0][arow] = a0.x; As[acol4 + 1][arow] = a0.y;
        As[acol4 + 2][arow] = a0.z; As[acol4 + 3][arow] = a0.w;
        As[acol4 + 0][arow + 64] = a1.x; As[acol4 + 1][arow + 64] = a1.y;
        As[acol4 + 2][arow + 64] = a1.z; As[acol4 + 3][arow + 64] = a1.w;
        *reinterpret_cast<float4*>(&Bs[brow][bcol4])     = b0;
        *reinterpret_cast<float4*>(&Bs[brow + 8][bcol4]) = b1;
        __syncthreads();

        #pragma unroll
        for (int k = 0; k < BK; k++) {
            float a[8], b[8];
            *reinterpret_cast<float4*>(&a[0]) = *reinterpret_cast<const float4*>(&As[k][ty * 8]);
            *reinterpret_cast<float4*>(&a[4]) = *reinterpret_cast<const float4*>(&As[k][ty * 8 + 4]);
            *reinterpret_cast<float4*>(&b[0]) = *reinterpret_cast<const float4*>(&Bs[k][tx * 8]);
            *reinterpret_cast<float4*>(&b[4]) = *reinterpret_cast<const float4*>(&Bs[k][tx * 8 + 4]);
            #pragma unroll
            for (int i = 0; i < 8; i++)
                #pragma unroll
                for (int j = 0; j < 8; j++)
                    acc[i][j] = fmaf(a[i], b[j], acc[i][j]);
        }
        __syncthreads();
    }

    float bb[8];
    *reinterpret_cast<float4*>(&bb[0]) = *reinterpret_cast<const float4*>(bias + tx * 8);
    *reinterpret_cast<float4*>(&bb[4]) = *reinterpret_cast<const float4*>(bias + tx * 8 + 4);

    #pragma unroll
    for (int i = 0; i < 8; i++) {
        int row = ty * 8 + i;
        float out[8];
        #pragma unroll
        for (int j = 0; j < 8; j++) {
            float v = acc[i][j] + bb[j];
            if (RELU) v = fmaxf(v, 0.f);
            out[j] = v;
        }
        *reinterpret_cast<float4*>(C + (size_t)row * N + tx * 8)     = *reinterpret_cast<float4*>(&out[0]);
        *reinterpret_cast<float4*>(C + (size_t)row * N + tx * 8 + 4) = *reinterpret_cast<float4*>(&out[4]);
    }
}

// ---------------- K6: gather / combine ----------------
__global__ void gather_kernel(float* __restrict__ out)
{
    int t = blockIdx.x;
    int s = g_slot[t];
    float4* dst = reinterpret_cast<float4*>(out + (size_t)t * MDIM);
    if (s < 0) {
        dst[threadIdx.x] = make_float4(0.f, 0.f, 0.f, 0.f);
        return;
    }
    float g = g_gate[t];
    float4 v = reinterpret_cast<const float4*>(g_oute + (size_t)s * MDIM)[threadIdx.x];
    dst[threadIdx.x] = make_float4(v.x * g, v.y * g, v.z * g, v.w * g);
}

// ---------------- launch ----------------
extern "C" void kernel_launch(void* const* d_in, const int* in_sizes, int n_in,
                              void* d_out, int out_size)
{
    const float* x  = (const float*)d_in[0];   // [4,2048,1024]
    const float* wg = (const float*)d_in[1];   // [1024,8]
    const float* w1 = (const float*)d_in[2];   // [8,1024,4096]
    const float* b1 = (const float*)d_in[3];   // [8,4096]
    const float* w2 = (const float*)d_in[4];   // [8,4096,1024]
    const float* b2 = (const float*)d_in[5];   // [8,1024]
    float* out = (float*)d_out;

    // Resolve device addresses of scratch globals (host shadow symbols are NOT
    // device pointers — this was the R1 bug). Host-side query; capture-safe.
    float *disp = nullptr, *h = nullptr, *oute = nullptr;
    cudaGetSymbolAddress((void**)&disp, g_disp);
    cudaGetSymbolAddress((void**)&h,    g_h);
    cudaGetSymbolAddress((void**)&oute, g_oute);

    // 1) gating: 8 warps/block
    gate_kernel<<<T_TOK / 8, 256>>>(x, wg);

    // 2) ordered positions + capacity drop
    pos_kernel<<<1, 1024>>>();

    // 3) scatter tokens -> g_disp
    scatter_kernel<<<T_TOK, 256>>>(x);

    // 4) GEMM1: h = relu(disp @ w1 + b1)   [1280,1024]x[1024,4096] per expert
    {
        dim3 grid(DFFD / 128, CAP / 128, NEXP);
        gemm128<true><<<grid, 256>>>(disp, w1, b1, h,
                                     DFFD, MDIM,
                                     (size_t)CAP * MDIM, (size_t)MDIM * DFFD,
                                     (size_t)CAP * DFFD, DFFD);
    }

    // 5) GEMM2: out_e = h @ w2 + b2        [1280,4096]x[4096,1024] per expert
    {
        dim3 grid(MDIM / 128, CAP / 128, NEXP);
        gemm128<false><<<grid, 256>>>(h, w2, b2, oute,
                                      MDIM, DFFD,
                                      (size_t)CAP * DFFD, (size_t)DFFD * MDIM,
                                      (size_t)CAP * MDIM, MDIM);
    }

    // 6) gather / combine
    gather_kernel<<<T_TOK, 256>>>(out);
}

// round 6
// speedup vs baseline: 2.6044x; 2.6044x over previous
#include <cuda_runtime.h>
#include <cstdint>

#define T_TOK 8192
#define MDIM  1024
#define NEXP  8
#define DFFD  4096
#define CAP   1280

// ---------------- device scratch ----------------
__device__ __align__(256) float g_disp[(size_t)NEXP * CAP * MDIM];   //  41.9 MB (tf32-rounded)
__device__ __align__(256) float g_h   [(size_t)NEXP * CAP * DFFD];   // 167.8 MB (tf32-rounded)
__device__ __align__(256) float g_oute[(size_t)NEXP * CAP * MDIM];   //  41.9 MB
__device__ int   g_expert[T_TOK];
__device__ float g_gate[T_TOK];
__device__ int   g_slot[T_TOK];

// ---------------- helpers ----------------
__device__ __forceinline__ uint32_t smem_u32(const void* p) {
    uint32_t a;
    asm("{ .reg .u64 t; cvta.to.shared.u64 t, %1; cvt.u32.u64 %0, t; }" : "=r"(a) : "l"(p));
    return a;
}
__device__ __forceinline__ float tf32r(float v) {
    uint32_t u;
    asm("cvt.rna.tf32.f32 %0, %1;" : "=r"(u) : "f"(v));
    return __uint_as_float(u);
}
__device__ __forceinline__ uint32_t tf32u(float v) {
    uint32_t u;
    asm("cvt.rna.tf32.f32 %0, %1;" : "=r"(u) : "f"(v));
    return u;
}

#define CPASYNC16(dst, src) \
    asm volatile("cp.async.cg.shared.global [%0], [%1], 16;" :: "r"(dst), "l"(src) : "memory")
#define CPCOMMIT()  asm volatile("cp.async.commit_group;" ::: "memory")
#define CPWAIT(n)   asm volatile("cp.async.wait_group %0;" :: "n"(n) : "memory")

// m16n8k8 tf32 mma: D += A*B (A row-major fragments, B col-major fragments)
__device__ __forceinline__ void mma_tf32(float* d, const uint32_t* a, const uint32_t* b) {
    asm volatile(
        "mma.sync.aligned.m16n8k8.row.col.f32.tf32.tf32.f32 "
        "{%0,%1,%2,%3}, {%4,%5,%6,%7}, {%8,%9}, {%0,%1,%2,%3};"
        : "+f"(d[0]), "+f"(d[1]), "+f"(d[2]), "+f"(d[3])
        : "r"(a[0]), "r"(a[1]), "r"(a[2]), "r"(a[3]), "r"(b[0]), "r"(b[1]));
}

// ---------------- K1: gating ----------------
__global__ void gate_kernel(const float* __restrict__ x, const float* __restrict__ wg)
{
    int warp = (blockIdx.x * blockDim.x + threadIdx.x) >> 5;
    int lane = threadIdx.x & 31;
    if (warp >= T_TOK) return;

    const float* xr = x + (size_t)warp * MDIM;
    float acc[8] = {0.f,0.f,0.f,0.f,0.f,0.f,0.f,0.f};

    #pragma unroll 4
    for (int i = 0; i < MDIM / 32; i++) {
        int m = i * 32 + lane;
        float xv = __ldg(xr + m);
        const float4* w4 = reinterpret_cast<const float4*>(wg + (size_t)m * NEXP);
        float4 a = w4[0], b = w4[1];
        acc[0] += xv * a.x; acc[1] += xv * a.y;
        acc[2] += xv * a.z; acc[3] += xv * a.w;
        acc[4] += xv * b.x; acc[5] += xv * b.y;
        acc[6] += xv * b.z; acc[7] += xv * b.w;
    }
    #pragma unroll
    for (int e = 0; e < 8; e++)
        #pragma unroll
        for (int off = 16; off > 0; off >>= 1)
            acc[e] += __shfl_xor_sync(0xffffffffu, acc[e], off);

    if (lane == 0) {
        float mx = acc[0]; int bi = 0;
        #pragma unroll
        for (int e = 1; e < 8; e++)
            if (acc[e] > mx) { mx = acc[e]; bi = e; }
        float s = 0.f;
        #pragma unroll
        for (int e = 0; e < 8; e++) s += expf(acc[e] - mx);
        g_expert[warp] = bi;
        g_gate[warp]   = 1.0f / s;
    }
}

// ---------------- K2: ordered per-expert rank ----------------
__global__ void pos_kernel()
{
    __shared__ int hist[1024][8];
    int tid = threadIdx.x;
    int base_t = tid * 8;

    int cnt[8] = {0,0,0,0,0,0,0,0};
    int loc[8];
    #pragma unroll
    for (int i = 0; i < 8; i++) {
        int e = g_expert[base_t + i];
        loc[i] = e;
        cnt[e]++;
    }
    #pragma unroll
    for (int e = 0; e < 8; e++) hist[tid][e] = cnt[e];
    __syncthreads();

    for (int off = 1; off < 1024; off <<= 1) {
        int v[8];
        bool p = (tid >= off);
        if (p) {
            #pragma unroll
            for (int e = 0; e < 8; e++) v[e] = hist[tid - off][e];
        }
        __syncthreads();
        if (p) {
            #pragma unroll
            for (int e = 0; e < 8; e++) hist[tid][e] += v[e];
        }
        __syncthreads();
    }

    int run[8];
    #pragma unroll
    for (int e = 0; e < 8; e++) run[e] = hist[tid][e] - cnt[e];

    #pragma unroll
    for (int i = 0; i < 8; i++) {
        int e = loc[i];
        int p = run[e]++;
        g_slot[base_t + i] = (p < CAP) ? (e * CAP + p) : -1;
    }
}

// ---------------- K3: scatter (+ tf32 rounding) ----------------
__global__ void scatter_kernel(const float* __restrict__ x)
{
    int t = blockIdx.x;
    int s = g_slot[t];
    if (s < 0) return;
    float4 v = reinterpret_cast<const float4*>(x + (size_t)t * MDIM)[threadIdx.x];
    v.x = tf32r(v.x); v.y = tf32r(v.y); v.z = tf32r(v.z); v.w = tf32r(v.w);
    reinterpret_cast<float4*>(g_disp + (size_t)s * MDIM)[threadIdx.x] = v;
}

// ---------------- K4: tf32 mma.sync GEMM ----------------
// C[128,128] tile = op(A[m,k] @ B[k,n] + bias[n])
// A row-major [rows, Kdim] (disp / h); B row-major [Kdim, Ndim] (w1 / w2 as-is)
// smem: As [128 rows][36] ; Bs [32 k-rows][132]  (both strides conflict-free:
//   A frag banks = 4g+tg via 36 mod 32 = 4-per-row walk; B frag banks = 4tg+g)
#define A_ST 4608   // 128*36 floats per stage
#define B_ST 4224   // 32*132 floats per stage
#define GEMM_SMEM ((2 * A_ST + 2 * B_ST) * 4)   // 70656 bytes

template<bool RELU, bool CVT>
__global__ void __launch_bounds__(256, 2)
moe_gemm(const float* __restrict__ Ag, const float* __restrict__ Bg,
         const float* __restrict__ biasg, float* __restrict__ Cg,
         int Ndim, int Kdim)
{
    extern __shared__ float sm[];
    const uint32_t su = smem_u32(sm);
    const int tid = threadIdx.x;
    const int wid = tid >> 5, lane = tid & 31;
    const int g = lane >> 2, tg = lane & 3;
    const int wm = (wid >> 2) * 64;          // warp row base: 0 / 64
    const int wn = (wid & 3) * 32;           // warp col base: 0/32/64/96

    const int z = blockIdx.z;
    const float* A = Ag + (size_t)z * CAP * Kdim + (size_t)(blockIdx.y * 128) * Kdim;
    const float* B = Bg + (size_t)z * Kdim * Ndim + blockIdx.x * 128;
    const float* bias = biasg + (size_t)z * Ndim + blockIdx.x * 128;
    float* C = Cg + (size_t)z * CAP * Ndim + (size_t)(blockIdx.y * 128) * Ndim + blockIdx.x * 128;

    // loader assignments
    const int arow = tid >> 1, acol = (tid & 1) * 16;      // A: 2 thr/row, 4x16B each
    const int brow = tid >> 3, bseg = (tid & 7) * 4;       // B: 8 thr/row, cols bseg+{0,32,64,96}

    float acc[4][4][4];
    #pragma unroll
    for (int i = 0; i < 4; i++)
        #pragma unroll
        for (int j = 0; j < 4; j++)
            #pragma unroll
            for (int q = 0; q < 4; q++) acc[i][j][q] = 0.f;

    auto load_stage = [&](int kt) {
        int s = kt & 1;
        const float* ag = A + (size_t)arow * Kdim + kt * 32 + acol;
        uint32_t ad = su + (uint32_t)(s * A_ST + arow * 36 + acol) * 4;
        #pragma unroll
        for (int i = 0; i < 4; i++)
            CPASYNC16(ad + i * 16, ag + i * 4);
        const float* bg = B + (size_t)(kt * 32 + brow) * Ndim + bseg;
        uint32_t bd = su + (uint32_t)(2 * A_ST + s * B_ST + brow * 132 + bseg) * 4;
        #pragma unroll
        for (int i = 0; i < 4; i++)
            CPASYNC16(bd + i * 128, bg + i * 32);   // +32 cols = +128 bytes
        CPCOMMIT();
    };

    load_stage(0);
    const int KT = Kdim >> 5;

    for (int kt = 0; kt < KT; kt++) {
        if (kt + 1 < KT) {
            load_stage(kt + 1);
            CPWAIT(1);
        } else {
            CPWAIT(0);
        }
        __syncthreads();

        const float* as = sm + (kt & 1) * A_ST;
        const float* bs = sm + 2 * A_ST + (kt & 1) * B_ST;

        #pragma unroll
        for (int ks = 0; ks < 4; ks++) {
            const int k0 = ks * 8;
            uint32_t afr[4][4], bfr[4][2];
            #pragma unroll
            for (int i = 0; i < 4; i++) {
                const float* ap = as + (wm + i * 16 + g) * 36 + k0 + tg;
                afr[i][0] = __float_as_uint(ap[0]);
                afr[i][1] = __float_as_uint(ap[8 * 36]);
                afr[i][2] = __float_as_uint(ap[4]);
                afr[i][3] = __float_as_uint(ap[8 * 36 + 4]);
            }
            #pragma unroll
            for (int j = 0; j < 4; j++) {
                const float* bp = bs + (k0 + tg) * 132 + wn + j * 8 + g;
                bfr[j][0] = tf32u(bp[0]);        // RNA-round weights to tf32
                bfr[j][1] = tf32u(bp[4 * 132]);
            }
            #pragma unroll
            for (int i = 0; i < 4; i++)
                #pragma unroll
                for (int j = 0; j < 4; j++)
                    mma_tf32(acc[i][j], afr[i], bfr[j]);
        }
        __syncthreads();
    }

    // epilogue
    #pragma unroll
    for (int j = 0; j < 4; j++) {
        const int col = wn + j * 8 + 2 * tg;
        float2 bv = *reinterpret_cast<const float2*>(bias + col);
        #pragma unroll
        for (int i = 0; i < 4; i++) {
            const int r0 = wm + i * 16 + g;
            float v00 = acc[i][j][0] + bv.x, v01 = acc[i][j][1] + bv.y;
            float v10 = acc[i][j][2] + bv.x, v11 = acc[i][j][3] + bv.y;
            if (RELU) {
                v00 = fmaxf(v00, 0.f); v01 = fmaxf(v01, 0.f);
                v10 = fmaxf(v10, 0.f); v11 = fmaxf(v11, 0.f);
            }
            if (CVT) {
                v00 = tf32r(v00); v01 = tf32r(v01);
                v10 = tf32r(v10); v11 = tf32r(v11);
            }
            *reinterpret_cast<float2*>(C + (size_t)r0 * Ndim + col) = make_float2(v00, v01);
            *reinterpret_cast<float2*>(C + (size_t)(r0 + 8) * Ndim + col) = make_float2(v10, v11);
        }
    }
}

// ---------------- K6: gather ----------------
__global__ void gather_kernel(float* __restrict__ out)
{
    int t = blockIdx.x;
    int s = g_slot[t];
    float4* dst = reinterpret_cast<float4*>(out + (size_t)t * MDIM);
    if (s < 0) {
        dst[threadIdx.x] = make_float4(0.f, 0.f, 0.f, 0.f);
        return;
    }
    float g = g_gate[t];
    float4 v = reinterpret_cast<const float4*>(g_oute + (size_t)s * MDIM)[threadIdx.x];
    dst[threadIdx.x] = make_float4(v.x * g, v.y * g, v.z * g, v.w * g);
}

// ---------------- launch ----------------
extern "C" void kernel_launch(void* const* d_in, const int* in_sizes, int n_in,
                              void* d_out, int out_size)
{
    const float* x  = (const float*)d_in[0];
    const float* wg = (const float*)d_in[1];
    const float* w1 = (const float*)d_in[2];   // [E, M, DFF]  -> B of GEMM1 ([k][n])
    const float* b1 = (const float*)d_in[3];
    const float* w2 = (const float*)d_in[4];   // [E, DFF, M]  -> B of GEMM2 ([k][n])
    const float* b2 = (const float*)d_in[5];
    float* out = (float*)d_out;

    float *disp, *h, *oute;
    cudaGetSymbolAddress((void**)&disp, g_disp);
    cudaGetSymbolAddress((void**)&h,    g_h);
    cudaGetSymbolAddress((void**)&oute, g_oute);

    cudaFuncSetAttribute(moe_gemm<true, true>,
                         cudaFuncAttributeMaxDynamicSharedMemorySize, GEMM_SMEM);
    cudaFuncSetAttribute(moe_gemm<false, false>,
                         cudaFuncAttributeMaxDynamicSharedMemorySize, GEMM_SMEM);

    gate_kernel<<<T_TOK / 8, 256>>>(x, wg);
    pos_kernel<<<1, 1024>>>();
    scatter_kernel<<<T_TOK, 256>>>(x);

    // GEMM1: h = relu(disp @ w1 + b1)   per-expert [1280,1024] x [1024,4096]
    moe_gemm<true, true><<<dim3(DFFD / 128, CAP / 128, NEXP), 256, GEMM_SMEM>>>(
        disp, w1, b1, h, DFFD, MDIM);

    // GEMM2: oute = h @ w2 + b2         per-expert [1280,4096] x [4096,1024]
    moe_gemm<false, false><<<dim3(MDIM / 128, CAP / 128, NEXP), 256, GEMM_SMEM>>>(
        h, w2, b2, oute, MDIM, DFFD);

    gather_kernel<<<T_TOK, 256>>>(out);
}